// round 5
// baseline (speedup 1.0000x reference)
#include <cuda_runtime.h>

#define BATCH 1024
#define TT    512
#define DIN   32
#define H     64
#define NROWS 256            // 4*H gate rows
#define NB    4              // batches per block in recurrent kernels
#define BT    (BATCH * TT)

// Static scratch: precomputed gate inputs + h1 stream.
__device__ float g_xg0[(size_t)BT * NROWS];   // 537 MB
__device__ float g_xg1[(size_t)BT * NROWS];   // 537 MB
__device__ float g_h1 [(size_t)BT * H];       // 134 MB

// ---------------------------------------------------------------------------
// helpers
// ---------------------------------------------------------------------------
__device__ __forceinline__ void ffma2(unsigned long long& acc,
                                      unsigned long long w,
                                      unsigned long long v) {
    asm("fma.rn.f32x2 %0, %1, %2, %0;" : "+l"(acc) : "l"(w), "l"(v));
}
__device__ __forceinline__ float f2lo(unsigned long long a) {
    return __uint_as_float((unsigned)(a & 0xffffffffull));
}
__device__ __forceinline__ float f2hi(unsigned long long a) {
    return __uint_as_float((unsigned)(a >> 32));
}
__device__ __forceinline__ unsigned long long packlo(float x) {
    return (unsigned long long)__float_as_uint(x);   // (x, 0)
}
__device__ __forceinline__ float tanh_f(float x) {
    // tanh(x) = 1 - 2/(e^{2x}+1); exact +-1 limits
    return 1.0f - __fdividef(2.0f, __expf(2.0f * x) + 1.0f);
}

// Gate row for output slot s: r = (s&3)*64 + (s>>2)  (PyTorch i,f,g,o order;
// recurrent kernel lane reads slot coalesced).
__device__ __forceinline__ int slot_row(int s) { return (s & 3) * H + (s >> 2); }

// ---------------------------------------------------------------------------
// GEMM: xg[row][slot] = input_row . W_ih[r(slot)] + bih[r] + bhh[r]
// (unchanged from R4 — runs near fp32 f32x2 peak)
// ---------------------------------------------------------------------------
template <int K>
__global__ void __launch_bounds__(128)
gemm_xg(const float* __restrict__ X,      // [BT][K]
        const float* __restrict__ Wih,    // [NROWS][K]
        const float* __restrict__ bih,
        const float* __restrict__ bhh,
        float* __restrict__ out)          // [BT][NROWS]
{
    constexpr int KP = K / 2;
    constexpr int ROWS = 128;
    __shared__ __align__(16) float xs[ROWS * K];

    const int tid = threadIdx.x;
    const int s0 = tid, s1 = tid + 128;
    const int r0 = slot_row(s0), r1 = slot_row(s1);

    unsigned long long w0[KP], w1[KP];
    #pragma unroll
    for (int i = 0; i < KP; i++) {
        w0[i] = reinterpret_cast<const unsigned long long*>(Wih + r0 * K)[i];
        w1[i] = reinterpret_cast<const unsigned long long*>(Wih + r1 * K)[i];
    }
    const float bias0 = bih[r0] + bhh[r0];
    const float bias1 = bih[r1] + bhh[r1];

    const size_t rowBase = (size_t)blockIdx.x * ROWS;

    const float4* src = reinterpret_cast<const float4*>(X + rowBase * K);
    float4* dst = reinterpret_cast<float4*>(xs);
    #pragma unroll
    for (int i = tid; i < ROWS * K / 4; i += 128) dst[i] = src[i];
    __syncthreads();

    #pragma unroll 2
    for (int row = 0; row < ROWS; row++) {
        const ulonglong2* xr = reinterpret_cast<const ulonglong2*>(xs + row * K);
        unsigned long long a0 = 0ull, a1 = 0ull;
        #pragma unroll
        for (int kk = 0; kk < KP / 2; kk++) {
            ulonglong2 xv = xr[kk];
            ffma2(a0, w0[2 * kk],     xv.x);
            ffma2(a0, w0[2 * kk + 1], xv.y);
            ffma2(a1, w1[2 * kk],     xv.x);
            ffma2(a1, w1[2 * kk + 1], xv.y);
        }
        float* o = out + (rowBase + row) * NROWS;
        o[s0] = bias0 + f2lo(a0) + f2hi(a0);
        o[s1] = bias1 + f2lo(a1) + f2hi(a1);
    }
}

// ---------------------------------------------------------------------------
// Split-K recurrent kernel. CTA = 512 threads, 2 CTAs/SM (<=64 regs).
// Lane layout within warp: half = bit4, j2 = bits3:2, g = bits1:0.
//   j = warp*4 + j2; slot = j*4+g; row = g*64+j.
// Each lane holds HALF a W_hh row (32 floats) and computes half-dots for all
// NB=4 batches; halves combine with shfl_xor(16). Lane owns batches
// {half, 2+half}: loads their xg, applies its gate's activation, and the
// (g==0) lane of each half updates c/h for its 2 owned batches.
// ---------------------------------------------------------------------------
template <bool FIRST>
__global__ void __launch_bounds__(512, 2)
lstm_rec(const float* __restrict__ xg,    // [BT][NROWS], bias folded in
         const float* __restrict__ Whh,   // [NROWS][H]
         float* __restrict__ h1out,       // FIRST: [BT][H]
         const float* __restrict__ Wfc,
         const float* __restrict__ bfc,
         float* __restrict__ out)         // !FIRST: [BATCH]
{
    __shared__ __align__(16) float hs[2][NB][H];

    const int tid  = threadIdx.x;
    const int lane = tid & 31;
    const int half = (lane >> 4) & 1;
    const int g    = lane & 3;
    const int j    = (tid >> 5) * 4 + ((lane >> 2) & 3);
    const int slot = j * 4 + g;
    const int r    = g * H + j;
    const int b0   = blockIdx.x * NB;
    const bool lead = (g == 0);

    // activation: act = alpha * tanh(beta * a) + gamma  (sigmoid for i,f,o)
    const bool g2 = (g == 2);
    const float alpha = g2 ? 1.0f : 0.5f;
    const float beta  = g2 ? 1.0f : 0.5f;
    const float gamma = g2 ? 0.0f : 0.5f;

    // half-row of W_hh (32 floats = 16 packed pairs)
    unsigned long long wh[16];
    {
        const unsigned long long* ws =
            reinterpret_cast<const unsigned long long*>(Whh + r * H + half * 32);
        #pragma unroll
        for (int i = 0; i < 16; i++) wh[i] = ws[i];
    }

    // owned batches: bA = half, bB = 2 + half
    const unsigned xoffA = (unsigned)((b0 + half) * TT) * NROWS + slot;
    const unsigned xoffB = (unsigned)((b0 + 2 + half) * TT) * NROWS + slot;
    const unsigned hoffA = (unsigned)((b0 + half) * TT) * H + j;
    const unsigned hoffB = (unsigned)((b0 + 2 + half) * TT) * H + j;

    float cA = 0.0f, cB = 0.0f;

    for (int i = tid; i < NB * H; i += 512) ((float*)hs[0])[i] = 0.0f;

    float xgcA = xg[xoffA];
    float xgcB = xg[xoffB];
    __syncthreads();

    const int base = lane & ~3;      // stays within the same half-group

    for (int t = 0; t < TT; t++) {
        const int cur = t & 1, nxt = cur ^ 1;

        // prefetch next step's xg for owned batches
        float xgnA = 0.0f, xgnB = 0.0f;
        if (t + 1 < TT) {
            xgnA = xg[xoffA + (unsigned)(t + 1) * NROWS];
            xgnB = xg[xoffB + (unsigned)(t + 1) * NROWS];
        }

        // half-dot accumulators for all 4 batches; owned xg folded in
        unsigned long long a0 = packlo(half ? 0.0f : xgcA);
        unsigned long long a1 = packlo(half ? xgcA : 0.0f);
        unsigned long long a2 = packlo(half ? 0.0f : xgcB);
        unsigned long long a3 = packlo(half ? xgcB : 0.0f);

        const float* hb = &hs[cur][0][half * 32];
        #pragma unroll
        for (int kk = 0; kk < 8; kk++) {
            ulonglong2 h0 = *reinterpret_cast<const ulonglong2*>(hb + 0 * H + kk * 4);
            ulonglong2 h1 = *reinterpret_cast<const ulonglong2*>(hb + 1 * H + kk * 4);
            ulonglong2 h2 = *reinterpret_cast<const ulonglong2*>(hb + 2 * H + kk * 4);
            ulonglong2 h3 = *reinterpret_cast<const ulonglong2*>(hb + 3 * H + kk * 4);
            ffma2(a0, wh[2 * kk], h0.x);  ffma2(a0, wh[2 * kk + 1], h0.y);
            ffma2(a1, wh[2 * kk], h1.x);  ffma2(a1, wh[2 * kk + 1], h1.y);
            ffma2(a2, wh[2 * kk], h2.x);  ffma2(a2, wh[2 * kk + 1], h2.y);
            ffma2(a3, wh[2 * kk], h3.x);  ffma2(a3, wh[2 * kk + 1], h3.y);
        }

        // combine halves (full gate pre-activations for all 4 batches)
        float s0 = f2lo(a0) + f2hi(a0); s0 += __shfl_xor_sync(0xffffffffu, s0, 16);
        float s1 = f2lo(a1) + f2hi(a1); s1 += __shfl_xor_sync(0xffffffffu, s1, 16);
        float s2 = f2lo(a2) + f2hi(a2); s2 += __shfl_xor_sync(0xffffffffu, s2, 16);
        float s3 = f2lo(a3) + f2hi(a3); s3 += __shfl_xor_sync(0xffffffffu, s3, 16);

        // activate own gate for the 2 owned batches
        const float actA = fmaf(alpha, tanh_f(beta * (half ? s1 : s0)), gamma);
        const float actB = fmaf(alpha, tanh_f(beta * (half ? s3 : s2)), gamma);

        // gather quad gates, update cells on lead lanes
        {
            float ai = __shfl_sync(0xffffffffu, actA, base + 0);
            float af = __shfl_sync(0xffffffffu, actA, base + 1);
            float ag = __shfl_sync(0xffffffffu, actA, base + 2);
            float ao = __shfl_sync(0xffffffffu, actA, base + 3);
            if (lead) {
                cA = fmaf(af, cA, ai * ag);
                float hh = ao * tanh_f(cA);
                hs[nxt][half][j] = hh;
                if (FIRST) h1out[hoffA + (unsigned)t * H] = hh;
            }
        }
        {
            float ai = __shfl_sync(0xffffffffu, actB, base + 0);
            float af = __shfl_sync(0xffffffffu, actB, base + 1);
            float ag = __shfl_sync(0xffffffffu, actB, base + 2);
            float ao = __shfl_sync(0xffffffffu, actB, base + 3);
            if (lead) {
                cB = fmaf(af, cB, ai * ag);
                float hh = ao * tanh_f(cB);
                hs[nxt][2 + half][j] = hh;
                if (FIRST) h1out[hoffB + (unsigned)t * H] = hh;
            }
        }

        xgcA = xgnA;
        xgcB = xgnB;
        __syncthreads();
    }

    if (!FIRST && tid < NB) {
        // final h is in hs[0] (TT even)
        float a = bfc[0];
        #pragma unroll
        for (int k = 0; k < H; k++) a = fmaf(hs[0][tid][k], Wfc[k], a);
        out[b0 + tid] = a;
    }
}

// ---------------------------------------------------------------------------
extern "C" void kernel_launch(void* const* d_in, const int* in_sizes, int n_in,
                              void* d_out, int out_size)
{
    const float* x    = (const float*)d_in[0];
    const float* Wih0 = (const float*)d_in[1];
    const float* Whh0 = (const float*)d_in[2];
    const float* bih0 = (const float*)d_in[3];
    const float* bhh0 = (const float*)d_in[4];
    const float* Wih1 = (const float*)d_in[5];
    const float* Whh1 = (const float*)d_in[6];
    const float* bih1 = (const float*)d_in[7];
    const float* bhh1 = (const float*)d_in[8];
    const float* Wfc  = (const float*)d_in[9];
    const float* bfc  = (const float*)d_in[10];
    float* out = (float*)d_out;

    float *xg0, *xg1, *h1;
    cudaGetSymbolAddress((void**)&xg0, g_xg0);
    cudaGetSymbolAddress((void**)&xg1, g_xg1);
    cudaGetSymbolAddress((void**)&h1,  g_h1);

    gemm_xg<DIN><<<BT / 128, 128>>>(x, Wih0, bih0, bhh0, xg0);
    lstm_rec<true><<<BATCH / NB, 512>>>(xg0, Whh0, h1, nullptr, nullptr, nullptr);
    gemm_xg<H><<<BT / 128, 128>>>(h1, Wih1, bih1, bhh1, xg1);
    lstm_rec<false><<<BATCH / NB, 512>>>(xg1, Whh1, nullptr, Wfc, bfc, out);
}

// round 7
// speedup vs baseline: 1.2262x; 1.2262x over previous
#include <cuda_runtime.h>

#define BATCH 1024
#define TT    512
#define DIN   32
#define H     64
#define NROWS 256
#define BT    (BATCH * TT)
#define HP    68          // padded h row stride (floats): conflict-free STS

typedef unsigned long long ull;

// Static scratch: precomputed gate inputs + h1 stream.
__device__ float g_xg0[(size_t)BT * NROWS];
__device__ float g_xg1[(size_t)BT * NROWS];
__device__ float g_h1 [(size_t)BT * H];

// ---------------------------------------------------------------------------
__device__ __forceinline__ void ffma2(ull& acc, ull w, ull v) {
    asm("fma.rn.f32x2 %0, %1, %2, %0;" : "+l"(acc) : "l"(w), "l"(v));
}
__device__ __forceinline__ float f2sum(ull a) {
    return __uint_as_float((unsigned)(a & 0xffffffffull)) +
           __uint_as_float((unsigned)(a >> 32));
}
__device__ __forceinline__ float tanh_f(float x) {
    return 1.0f - __fdividef(2.0f, __expf(2.0f * x) + 1.0f);
}
__device__ __forceinline__ float sigm(float x) {
    return __fdividef(1.0f, 1.0f + __expf(-x));
}
__device__ __forceinline__ int slot_row(int s) { return (s & 3) * H + (s >> 2); }

// ---------------------------------------------------------------------------
// GEMM K=32 (layer-0 input part). R4 design: 128 thr, 2 slots/thread.
// ---------------------------------------------------------------------------
__global__ void __launch_bounds__(128)
gemm_xg32(const float* __restrict__ X, const float* __restrict__ Wih,
          const float* __restrict__ bih, const float* __restrict__ bhh,
          float* __restrict__ out)
{
    constexpr int K = 32, ROWS = 128;
    __shared__ __align__(16) float xs[ROWS * K];

    const int tid = threadIdx.x;
    const int s0 = tid, s1 = tid + 128;
    const int r0 = slot_row(s0), r1 = slot_row(s1);

    ull w0[K / 2], w1[K / 2];
    #pragma unroll
    for (int i = 0; i < K / 2; i++) {
        w0[i] = reinterpret_cast<const ull*>(Wih + r0 * K)[i];
        w1[i] = reinterpret_cast<const ull*>(Wih + r1 * K)[i];
    }
    const float bias0 = bih[r0] + bhh[r0];
    const float bias1 = bih[r1] + bhh[r1];

    const size_t rowBase = (size_t)blockIdx.x * ROWS;
    const float4* src = reinterpret_cast<const float4*>(X + rowBase * K);
    float4* dst = reinterpret_cast<float4*>(xs);
    #pragma unroll
    for (int i = tid; i < ROWS * K / 4; i += 128) dst[i] = src[i];
    __syncthreads();

    #pragma unroll 2
    for (int row = 0; row < ROWS; row++) {
        const ulonglong2* xr = reinterpret_cast<const ulonglong2*>(xs + row * K);
        ull a0 = 0ull, a1 = 0ull;
        #pragma unroll
        for (int kk = 0; kk < K / 4; kk++) {
            ulonglong2 xv = xr[kk];
            ffma2(a0, w0[2 * kk], xv.x);  ffma2(a0, w0[2 * kk + 1], xv.y);
            ffma2(a1, w1[2 * kk], xv.x);  ffma2(a1, w1[2 * kk + 1], xv.y);
        }
        float* o = out + (rowBase + row) * NROWS;
        o[s0] = bias0 + f2sum(a0);
        o[s1] = bias1 + f2sum(a1);
    }
}

// ---------------------------------------------------------------------------
// GEMM K=64 (layer-1 input part), split-K by halves so weights fit (64 regs).
// 256 thr: lane bit4 = half; pid = warp*16 + lane&15 (slot pair pid, pid+128).
// ---------------------------------------------------------------------------
__global__ void __launch_bounds__(256)
gemm_xg64(const float* __restrict__ X, const float* __restrict__ Wih,
          const float* __restrict__ bih, const float* __restrict__ bhh,
          float* __restrict__ out)
{
    constexpr int K = 64, ROWS = 128;
    __shared__ __align__(16) float xs[ROWS * K];   // 32 KB

    const int tid  = threadIdx.x;
    const int lane = tid & 31;
    const int wrp  = tid >> 5;
    const int half = (lane >> 4) & 1;
    const int pid  = wrp * 16 + (lane & 15);
    const int s0 = pid, s1 = pid + 128;
    const int r0 = slot_row(s0), r1 = slot_row(s1);

    ull w0[16], w1[16];
    #pragma unroll
    for (int i = 0; i < 16; i++) {
        w0[i] = reinterpret_cast<const ull*>(Wih + r0 * K + half * 32)[i];
        w1[i] = reinterpret_cast<const ull*>(Wih + r1 * K + half * 32)[i];
    }
    const float bias  = half ? (bih[r1] + bhh[r1]) : (bih[r0] + bhh[r0]);
    const int myslot  = half ? s1 : s0;

    const size_t rowBase = (size_t)blockIdx.x * ROWS;
    const float4* src = reinterpret_cast<const float4*>(X + rowBase * K);
    float4* dst = reinterpret_cast<float4*>(xs);
    #pragma unroll
    for (int i = tid; i < ROWS * K / 4; i += 256) dst[i] = src[i];
    __syncthreads();

    #pragma unroll 2
    for (int row = 0; row < ROWS; row++) {
        const ulonglong2* xr =
            reinterpret_cast<const ulonglong2*>(xs + row * K + half * 32);
        ull a0 = 0ull, a1 = 0ull;
        #pragma unroll
        for (int kk = 0; kk < 8; kk++) {
            ulonglong2 xv = xr[kk];
            ffma2(a0, w0[2 * kk], xv.x);  ffma2(a0, w0[2 * kk + 1], xv.y);
            ffma2(a1, w1[2 * kk], xv.x);  ffma2(a1, w1[2 * kk + 1], xv.y);
        }
        float v0 = f2sum(a0), v1 = f2sum(a1);
        float send = half ? v0 : v1;
        float recv = __shfl_xor_sync(0xffffffffu, send, 16);
        float mine = (half ? v1 : v0) + recv;
        out[(rowBase + row) * NROWS + myslot] = bias + mine;
    }
}

// ---------------------------------------------------------------------------
// Recurrent kernel: 512 thr, NB=8, grid=128, 1 CTA/SM.
// lane bits: gp = b0, jlow = b2:1, q = b4:3.  j = warp*4 + jlow.
// Thread holds 2 gate rows (gp=0: i,g ; gp=1: f,o) x quarter-K q (16 k).
// 3-round butterfly (xor8, xor16 over q; xor1 over gp) delivers all 4 gate
// pre-acts of batch b_own = 4*q1 + 2*q0 + gp to one lane, which owns c.
// ---------------------------------------------------------------------------
template <bool FIRST>
__global__ void __launch_bounds__(512, 1)
lstm_rec(const float* __restrict__ xg,    // [BT][NROWS], bias folded in
         const float* __restrict__ Whh,   // [NROWS][H]
         float* __restrict__ h1out,
         const float* __restrict__ Wfc,
         const float* __restrict__ bfc,
         float* __restrict__ out)
{
    __shared__ __align__(16) float hs[2][8 * HP];

    const int tid  = threadIdx.x;
    const int lane = tid & 31;
    const int wrp  = tid >> 5;
    const int gp   = lane & 1;
    const int jlow = (lane >> 1) & 3;
    const int q    = (lane >> 3) & 3;
    const int q0   = q & 1, q1 = (q >> 1) & 1;
    const int j    = wrp * 4 + jlow;
    const int b_own = 4 * q1 + 2 * q0 + gp;
    const int b0   = blockIdx.x * 8;

    const int rA = gp * H + j;          // gate i (gp=0) or f (gp=1)
    const int rB = (gp + 2) * H + j;    // gate g (gp=0) or o (gp=1)

    ull wA[8], wB[8];
    #pragma unroll
    for (int i = 0; i < 8; i++) {
        wA[i] = reinterpret_cast<const ull*>(Whh + rA * H + q * 16)[i];
        wB[i] = reinterpret_cast<const ull*>(Whh + rB * H + q * 16)[i];
    }

    const float* xgp = xg + ((size_t)(b0 + b_own) * TT) * NROWS + j * 4;
    float* h1p = h1out + ((size_t)(b0 + b_own) * TT) * H + j;

    float c = 0.0f;
    for (int i = tid; i < 8 * HP; i += 512) hs[0][i] = 0.0f;

    float4 xg4 = *reinterpret_cast<const float4*>(xgp);
    __syncthreads();

    for (int t = 0; t < TT; t++) {
        const int cur = t & 1, nxt = cur ^ 1;

        float4 xg4n;
        if (t + 1 < TT)
            xg4n = *reinterpret_cast<const float4*>(xgp + (size_t)(t + 1) * NROWS);

        // quarter-dots for all 8 batches, 2 rows each
        float sA[8], sB[8];
        const float* hq = hs[cur] + q * 16;
        #pragma unroll
        for (int b = 0; b < 8; b++) {
            const ulonglong2* hb =
                reinterpret_cast<const ulonglong2*>(hq + b * HP);
            ulonglong2 h0 = hb[0], h1v = hb[1], h2 = hb[2], h3 = hb[3];
            ull aA = 0ull, aB = 0ull;
            ffma2(aA, wA[0], h0.x);  ffma2(aA, wA[1], h0.y);
            ffma2(aA, wA[2], h1v.x); ffma2(aA, wA[3], h1v.y);
            ffma2(aA, wA[4], h2.x);  ffma2(aA, wA[5], h2.y);
            ffma2(aA, wA[6], h3.x);  ffma2(aA, wA[7], h3.y);
            ffma2(aB, wB[0], h0.x);  ffma2(aB, wB[1], h0.y);
            ffma2(aB, wB[2], h1v.x); ffma2(aB, wB[3], h1v.y);
            ffma2(aB, wB[4], h2.x);  ffma2(aB, wB[5], h2.y);
            ffma2(aB, wB[6], h3.x);  ffma2(aB, wB[7], h3.y);
            sA[b] = f2sum(aA);
            sB[b] = f2sum(aB);
        }

        // round 1: xor 8 (q0) — keep batches with b1 == q0
        float tA[4], tB[4];
        {
            // pairs (x,y) = (0,2),(1,3),(4,6),(5,7); t[pi] <-> b = 2*q0 + (pi&1) + 4*(pi>>1)
            #define RND1(sv, tv, x, y, pi)                                      \
                { float snd = q0 ? sv[x] : sv[y];                               \
                  float rcv = __shfl_xor_sync(0xffffffffu, snd, 8);             \
                  tv[pi] = (q0 ? sv[y] : sv[x]) + rcv; }
            RND1(sA, tA, 0, 2, 0) RND1(sA, tA, 1, 3, 1)
            RND1(sA, tA, 4, 6, 2) RND1(sA, tA, 5, 7, 3)
            RND1(sB, tB, 0, 2, 0) RND1(sB, tB, 1, 3, 1)
            RND1(sB, tB, 4, 6, 2) RND1(sB, tB, 5, 7, 3)
            #undef RND1
        }
        // round 2: xor 16 (q1) — keep b2 == q1;  u[jj] <-> b = 4*q1 + 2*q0 + jj
        float uA[2], uB[2];
        {
            #define RND2(tv, uv, jj)                                            \
                { float snd = q1 ? tv[jj] : tv[jj + 2];                         \
                  float rcv = __shfl_xor_sync(0xffffffffu, snd, 16);            \
                  uv[jj] = (q1 ? tv[jj + 2] : tv[jj]) + rcv; }
            RND2(tA, uA, 0) RND2(tA, uA, 1)
            RND2(tB, uB, 0) RND2(tB, uB, 1)
            #undef RND2
        }
        // round 3: xor 1 (gp) — swap the non-owned batch's two gates
        float sendA = gp ? uA[0] : uA[1];
        float sendB = gp ? uB[0] : uB[1];
        float recvA = __shfl_xor_sync(0xffffffffu, sendA, 1);
        float recvB = __shfl_xor_sync(0xffffffffu, sendB, 1);
        float mineA = gp ? uA[1] : uA[0];
        float mineB = gp ? uB[1] : uB[0];

        float gi = (gp ? recvA : mineA) + xg4.x;
        float gf = (gp ? mineA : recvA) + xg4.y;
        float gg = (gp ? recvB : mineB) + xg4.z;
        float go = (gp ? mineB : recvB) + xg4.w;

        c = fmaf(sigm(gf), c, sigm(gi) * tanh_f(gg));
        float hh = sigm(go) * tanh_f(c);
        hs[nxt][b_own * HP + j] = hh;
        if (FIRST) h1p[(size_t)t * H] = hh;

        xg4 = xg4n;
        __syncthreads();
    }

    if (!FIRST && tid < 8) {
        float a = bfc[0];
        #pragma unroll
        for (int k = 0; k < H; k++) a = fmaf(hs[0][tid * HP + k], Wfc[k], a);
        out[b0 + tid] = a;
    }
}

// ---------------------------------------------------------------------------
extern "C" void kernel_launch(void* const* d_in, const int* in_sizes, int n_in,
                              void* d_out, int out_size)
{
    const float* x    = (const float*)d_in[0];
    const float* Wih0 = (const float*)d_in[1];
    const float* Whh0 = (const float*)d_in[2];
    const float* bih0 = (const float*)d_in[3];
    const float* bhh0 = (const float*)d_in[4];
    const float* Wih1 = (const float*)d_in[5];
    const float* Whh1 = (const float*)d_in[6];
    const float* bih1 = (const float*)d_in[7];
    const float* bhh1 = (const float*)d_in[8];
    const float* Wfc  = (const float*)d_in[9];
    const float* bfc  = (const float*)d_in[10];
    float* out = (float*)d_out;

    float *xg0, *xg1, *h1;
    cudaGetSymbolAddress((void**)&xg0, g_xg0);
    cudaGetSymbolAddress((void**)&xg1, g_xg1);
    cudaGetSymbolAddress((void**)&h1,  g_h1);

    gemm_xg32<<<BT / 128, 128>>>(x, Wih0, bih0, bhh0, xg0);
    lstm_rec<true><<<BATCH / 8, 512>>>(xg0, Whh0, h1, nullptr, nullptr, nullptr);
    gemm_xg64<<<BT / 128, 256>>>(h1, Wih1, bih1, bhh1, xg1);
    lstm_rec<false><<<BATCH / 8, 512>>>(xg1, Whh1, h1, Wfc, bfc, out);
}

// round 8
// speedup vs baseline: 1.2307x; 1.0036x over previous
#include <cuda_runtime.h>

#define BATCH 1024
#define TT    512
#define DIN   32
#define H     64
#define NROWS 256
#define BT    (BATCH * TT)
#define HP    72          // padded h row stride: conflict-free STS/LDS

typedef unsigned long long ull;

__device__ float g_xg0[(size_t)BT * NROWS];
__device__ float g_xg1[(size_t)BT * NROWS];
__device__ float g_h1 [(size_t)BT * H];

// ---------------------------------------------------------------------------
__device__ __forceinline__ void ffma2(ull& acc, ull w, ull v) {
    asm("fma.rn.f32x2 %0, %1, %2, %0;" : "+l"(acc) : "l"(w), "l"(v));
}
__device__ __forceinline__ float f2sum(ull a) {
    return __uint_as_float((unsigned)(a & 0xffffffffull)) +
           __uint_as_float((unsigned)(a >> 32));
}
__device__ __forceinline__ float tanh_f(float x) {
    return 1.0f - __fdividef(2.0f, __expf(2.0f * x) + 1.0f);
}
__device__ __forceinline__ float sigm(float x) {
    return __fdividef(1.0f, 1.0f + __expf(-x));
}
__device__ __forceinline__ int slot_row(int s) { return (s & 3) * H + (s >> 2); }

// ---------------------------------------------------------------------------
// GEMM K=32 (layer-0 input part): 128 thr, 2 slots/thread.
// ---------------------------------------------------------------------------
__global__ void __launch_bounds__(128)
gemm_xg32(const float* __restrict__ X, const float* __restrict__ Wih,
          const float* __restrict__ bih, const float* __restrict__ bhh,
          float* __restrict__ out)
{
    constexpr int K = 32, ROWS = 128;
    __shared__ __align__(16) float xs[ROWS * K];

    const int tid = threadIdx.x;
    const int s0 = tid, s1 = tid + 128;
    const int r0 = slot_row(s0), r1 = slot_row(s1);

    ull w0[K / 2], w1[K / 2];
    #pragma unroll
    for (int i = 0; i < K / 2; i++) {
        w0[i] = reinterpret_cast<const ull*>(Wih + r0 * K)[i];
        w1[i] = reinterpret_cast<const ull*>(Wih + r1 * K)[i];
    }
    const float bias0 = bih[r0] + bhh[r0];
    const float bias1 = bih[r1] + bhh[r1];

    const size_t rowBase = (size_t)blockIdx.x * ROWS;
    const float4* src = reinterpret_cast<const float4*>(X + rowBase * K);
    float4* dst = reinterpret_cast<float4*>(xs);
    #pragma unroll
    for (int i = tid; i < ROWS * K / 4; i += 128) dst[i] = src[i];
    __syncthreads();

    #pragma unroll 2
    for (int row = 0; row < ROWS; row++) {
        const ulonglong2* xr = reinterpret_cast<const ulonglong2*>(xs + row * K);
        ull a0 = 0ull, a1 = 0ull;
        #pragma unroll
        for (int kk = 0; kk < K / 4; kk++) {
            ulonglong2 xv = xr[kk];
            ffma2(a0, w0[2 * kk], xv.x);  ffma2(a0, w0[2 * kk + 1], xv.y);
            ffma2(a1, w1[2 * kk], xv.x);  ffma2(a1, w1[2 * kk + 1], xv.y);
        }
        float* o = out + (rowBase + row) * NROWS;
        o[s0] = bias0 + f2sum(a0);
        o[s1] = bias1 + f2sum(a1);
    }
}

// ---------------------------------------------------------------------------
// GEMM K=64 (layer-1 input part), split-K halves, shfl_xor(16) combine.
// ---------------------------------------------------------------------------
__global__ void __launch_bounds__(256)
gemm_xg64(const float* __restrict__ X, const float* __restrict__ Wih,
          const float* __restrict__ bih, const float* __restrict__ bhh,
          float* __restrict__ out)
{
    constexpr int K = 64, ROWS = 128;
    __shared__ __align__(16) float xs[ROWS * K];

    const int tid  = threadIdx.x;
    const int lane = tid & 31;
    const int wrp  = tid >> 5;
    const int half = (lane >> 4) & 1;
    const int pid  = wrp * 16 + (lane & 15);
    const int s0 = pid, s1 = pid + 128;
    const int r0 = slot_row(s0), r1 = slot_row(s1);

    ull w0[16], w1[16];
    #pragma unroll
    for (int i = 0; i < 16; i++) {
        w0[i] = reinterpret_cast<const ull*>(Wih + r0 * K + half * 32)[i];
        w1[i] = reinterpret_cast<const ull*>(Wih + r1 * K + half * 32)[i];
    }
    const float bias  = half ? (bih[r1] + bhh[r1]) : (bih[r0] + bhh[r0]);
    const int myslot  = half ? s1 : s0;

    const size_t rowBase = (size_t)blockIdx.x * ROWS;
    const float4* src = reinterpret_cast<const float4*>(X + rowBase * K);
    float4* dst = reinterpret_cast<float4*>(xs);
    #pragma unroll
    for (int i = tid; i < ROWS * K / 4; i += 256) dst[i] = src[i];
    __syncthreads();

    #pragma unroll 2
    for (int row = 0; row < ROWS; row++) {
        const ulonglong2* xr =
            reinterpret_cast<const ulonglong2*>(xs + row * K + half * 32);
        ull a0 = 0ull, a1 = 0ull;
        #pragma unroll
        for (int kk = 0; kk < 8; kk++) {
            ulonglong2 xv = xr[kk];
            ffma2(a0, w0[2 * kk], xv.x);  ffma2(a0, w0[2 * kk + 1], xv.y);
            ffma2(a1, w1[2 * kk], xv.x);  ffma2(a1, w1[2 * kk + 1], xv.y);
        }
        float v0 = f2sum(a0), v1 = f2sum(a1);
        float send = half ? v0 : v1;
        float recv = __shfl_xor_sync(0xffffffffu, send, 16);
        float mine = (half ? v1 : v0) + recv;
        out[(rowBase + row) * NROWS + myslot] = bias + mine;
    }
}

// ---------------------------------------------------------------------------
// Recurrent kernel: 256 thr, NB=4, grid=256, 2 CTAs/SM.
// lane bits: jlow = b2:0, q0 = b3, q1 = b4.  j = warp*8 + jlow, q = 2*q1+q0.
// Thread holds ALL 4 gate rows of its j over K-quarter q (64 weight regs).
// 2-round butterfly (xor8 over q0, xor16 over q1) sums quarters and lands the
// 4 complete gate pre-acts of batch b_own = q on this thread. No gate-gather
// round: activations + cell update happen in place. One barrier per step.
// ---------------------------------------------------------------------------
template <bool FIRST>
__global__ void __launch_bounds__(256, 2)
lstm_rec(const float* __restrict__ xg,    // [BT][NROWS], bias folded in
         const float* __restrict__ Whh,   // [NROWS][H]
         float* __restrict__ h1out,
         const float* __restrict__ Wfc,
         const float* __restrict__ bfc,
         float* __restrict__ out)
{
    __shared__ __align__(16) float hs[2][4 * HP];

    const int tid  = threadIdx.x;
    const int lane = tid & 31;
    const int wrp  = tid >> 5;
    const int jlow = lane & 7;
    const int q0   = (lane >> 3) & 1;
    const int q1   = (lane >> 4) & 1;
    const int q    = 2 * q1 + q0;
    const int j    = wrp * 8 + jlow;
    const int b0   = blockIdx.x * 4;

    // all 4 gate rows of j, quarter q: w[g][0..7] packed pairs
    ull w[4][8];
    #pragma unroll
    for (int g = 0; g < 4; g++) {
        const ull* ws = reinterpret_cast<const ull*>(Whh + (g * H + j) * H + q * 16);
        #pragma unroll
        for (int i = 0; i < 8; i++) w[g][i] = ws[i];
    }

    const float* xgp = xg + ((size_t)(b0 + q) * TT) * NROWS + j * 4;
    float* h1p = FIRST ? (h1out + ((size_t)(b0 + q) * TT) * H + j) : nullptr;

    float c = 0.0f;
    for (int i = tid; i < 4 * HP; i += 256) hs[0][i] = 0.0f;

    float4 xg4 = *reinterpret_cast<const float4*>(xgp);
    __syncthreads();

    for (int t = 0; t < TT; t++) {
        const int cur = t & 1, nxt = cur ^ 1;

        float4 xg4n;
        if (t + 1 < TT)
            xg4n = *reinterpret_cast<const float4*>(xgp + (size_t)(t + 1) * NROWS);

        // quarter-dots: s[g][b] for 4 gates x 4 batches
        float s[4][4];
        const float* hq = hs[cur] + q * 16;
        #pragma unroll
        for (int b = 0; b < 4; b++) {
            const ulonglong2* hb = reinterpret_cast<const ulonglong2*>(hq + b * HP);
            ulonglong2 h0 = hb[0], h1v = hb[1], h2 = hb[2], h3 = hb[3];
            #pragma unroll
            for (int g = 0; g < 4; g++) {
                ull a = 0ull;
                ffma2(a, w[g][0], h0.x);  ffma2(a, w[g][1], h0.y);
                ffma2(a, w[g][2], h1v.x); ffma2(a, w[g][3], h1v.y);
                ffma2(a, w[g][4], h2.x);  ffma2(a, w[g][5], h2.y);
                ffma2(a, w[g][6], h3.x);  ffma2(a, w[g][7], h3.y);
                s[g][b] = f2sum(a);
            }
        }

        // round 1: xor 8 (q0) — keep b with b0 == q0; t_[g][p] <-> b = 2p + q0
        float t_[4][2];
        #pragma unroll
        for (int g = 0; g < 4; g++) {
            #pragma unroll
            for (int p = 0; p < 2; p++) {
                float snd = q0 ? s[g][2 * p] : s[g][2 * p + 1];
                float rcv = __shfl_xor_sync(0xffffffffu, snd, 8);
                t_[g][p] = (q0 ? s[g][2 * p + 1] : s[g][2 * p]) + rcv;
            }
        }
        // round 2: xor 16 (q1) — keep b = 2*q1 + q0 == q
        float u[4];
        #pragma unroll
        for (int g = 0; g < 4; g++) {
            float snd = q1 ? t_[g][0] : t_[g][1];
            float rcv = __shfl_xor_sync(0xffffffffu, snd, 16);
            u[g] = (q1 ? t_[g][1] : t_[g][0]) + rcv;
        }

        // full gate pre-acts of (b_own = q, j)
        float gi = u[0] + xg4.x;
        float gf = u[1] + xg4.y;
        float gg = u[2] + xg4.z;
        float go = u[3] + xg4.w;

        c = fmaf(sigm(gf), c, sigm(gi) * tanh_f(gg));
        float hh = sigm(go) * tanh_f(c);
        hs[nxt][q * HP + j] = hh;
        if (FIRST) h1p[(size_t)t * H] = hh;

        xg4 = xg4n;
        __syncthreads();
    }

    if (!FIRST && tid < 4) {
        float a = bfc[0];
        #pragma unroll
        for (int k = 0; k < H; k++) a = fmaf(hs[0][tid * HP + k], Wfc[k], a);
        out[b0 + tid] = a;
    }
}

// ---------------------------------------------------------------------------
extern "C" void kernel_launch(void* const* d_in, const int* in_sizes, int n_in,
                              void* d_out, int out_size)
{
    const float* x    = (const float*)d_in[0];
    const float* Wih0 = (const float*)d_in[1];
    const float* Whh0 = (const float*)d_in[2];
    const float* bih0 = (const float*)d_in[3];
    const float* bhh0 = (const float*)d_in[4];
    const float* Wih1 = (const float*)d_in[5];
    const float* Whh1 = (const float*)d_in[6];
    const float* bih1 = (const float*)d_in[7];
    const float* bhh1 = (const float*)d_in[8];
    const float* Wfc  = (const float*)d_in[9];
    const float* bfc  = (const float*)d_in[10];
    float* out = (float*)d_out;

    float *xg0, *xg1, *h1;
    cudaGetSymbolAddress((void**)&xg0, g_xg0);
    cudaGetSymbolAddress((void**)&xg1, g_xg1);
    cudaGetSymbolAddress((void**)&h1,  g_h1);

    gemm_xg32<<<BT / 128, 128>>>(x, Wih0, bih0, bhh0, xg0);
    lstm_rec<true><<<BATCH / 4, 256>>>(xg0, Whh0, h1, nullptr, nullptr, nullptr);
    gemm_xg64<<<BT / 128, 256>>>(h1, Wih1, bih1, bhh1, xg1);
    lstm_rec<false><<<BATCH / 4, 256>>>(xg1, Whh1, nullptr, Wfc, bfc, out);
}